// round 11
// baseline (speedup 1.0000x reference)
#include <cuda_runtime.h>
#include <cstddef>

#define NQ    40000
#define D     256
#define BEVH  200
#define BEVW  200
#define NH    8
#define NP    8
#define HD    32
#define DFF   1024

typedef unsigned long long u64;

// ---------------- scratch (static device globals; no allocation) ------------
__device__ float g_off [ (size_t)NQ * (NH*NP*2) ];   // 40000 x 128
__device__ float g_attn[ (size_t)NQ * (NH*NP)   ];   // 40000 x 64
__device__ float g_ref [ (size_t)NQ * 2         ];   // 40000 x 2
__device__ float g_vsum[ (size_t)NQ * D         ];   // 40000 x 256 (val0+val1)
__device__ float g_att [ (size_t)NQ * D         ];   // 40000 x 256 (attended sum)
__device__ float g_ffh [ (size_t)NQ * DFF       ];   // 40000 x 1024

// ---------------- f32x2 packed-FMA helpers (sm_103a FFMA2) ------------------
__device__ __forceinline__ u64 pack2(float lo, float hi) {
    u64 r;
    asm("mov.b64 %0, {%1, %2};" : "=l"(r) : "f"(lo), "f"(hi));
    return r;
}
__device__ __forceinline__ void unpack2(u64 v, float& lo, float& hi) {
    asm("mov.b64 {%0, %1}, %2;" : "=f"(lo), "=f"(hi) : "l"(v));
}
__device__ __forceinline__ void fma2(u64& d, u64 a, u64 b) {
    asm("fma.rn.f32x2 %0, %1, %2, %0;" : "+l"(d) : "l"(a), "l"(b));
}

// ---------------- tiled fp32 GEMM, f32x2 inner product, fused epilogue ------
// C[M,N] = (A (+A2)) @ W[K,N] + bias_scale*bias + res_scale*R ; optional relu
// 128x128 block tile, 256 threads, 8x8 micro-tile (f32x2 pairs along M),
// double-buffered shared memory: ONE __syncthreads per k-tile.
#define BM 128
#define BN 128
#define BK 16
#define TM 8
#define TN 8
#define ASTRIDE (BM + 2)   // +2 pad: conflict-free transposed stores, 8B-aligned reads

__global__ void __launch_bounds__(256, 2)
gemm_kernel(const float* __restrict__ A, const float* __restrict__ A2,
            const float* __restrict__ W, const float* __restrict__ bias,
            float bias_scale,
            const float* __restrict__ R, float res_scale, int relu,
            float* __restrict__ C, int M, int N, int K)
{
    __shared__ float As[2][BK][ASTRIDE];   // As[s][k][m]
    __shared__ float Bs[2][BK][BN];        // Bs[s][k][n]
    const int tid = threadIdx.x;
    const int tx = tid & 15;        // 0..15 -> N (8 cols each)
    const int ty = tid >> 4;        // 0..15 -> M (8 rows each)
    const int m0 = blockIdx.y * BM;
    const int n0 = blockIdx.x * BN;

    u64 acc2[TM/2][TN];
#pragma unroll
    for (int i = 0; i < TM/2; i++)
#pragma unroll
        for (int j = 0; j < TN; j++) acc2[i][j] = 0ull;

    // A-tile loader: 2 float4 per thread. W-tile loader: 2 float4 per thread.
    const int a_row = tid >> 2;          // 0..63
    const int a_col = (tid & 3) * 4;     // 0,4,8,12
    const int w_row = tid >> 4;          // 0..15
    const int w_col = (tid & 15) * 8;    // 0..120

    float4 av[2], wv[2];

    auto load_tile = [&](int k0) {
#pragma unroll
        for (int r = 0; r < 2; r++) {
            int gm = m0 + a_row + r * 64;
            float4 v = make_float4(0.f, 0.f, 0.f, 0.f);
            if (gm < M) {
                v = *(const float4*)&A[(size_t)gm * K + k0 + a_col];
                if (A2) {
                    float4 v2 = *(const float4*)&A2[(size_t)gm * K + k0 + a_col];
                    v.x += v2.x; v.y += v2.y; v.z += v2.z; v.w += v2.w;
                }
            }
            av[r] = v;
        }
#pragma unroll
        for (int r = 0; r < 2; r++) {
            int gn = n0 + w_col + r * 4;
            wv[r] = (gn < N)
                ? *(const float4*)&W[(size_t)(k0 + w_row) * N + gn]
                : make_float4(0.f, 0.f, 0.f, 0.f);
        }
    };
    auto store_tile = [&](int s) {
#pragma unroll
        for (int r = 0; r < 2; r++) {
            As[s][a_col + 0][a_row + r * 64] = av[r].x;
            As[s][a_col + 1][a_row + r * 64] = av[r].y;
            As[s][a_col + 2][a_row + r * 64] = av[r].z;
            As[s][a_col + 3][a_row + r * 64] = av[r].w;
        }
        *(float4*)&Bs[s][w_row][w_col]     = wv[0];
        *(float4*)&Bs[s][w_row][w_col + 4] = wv[1];
    };
    auto compute_tile = [&](int s) {
#pragma unroll
        for (int k = 0; k < BK; k++) {
            const u64* Ap = (const u64*)&As[s][k][ty * TM];
            u64 ra2[TM/2];
#pragma unroll
            for (int i = 0; i < TM/2; i++) ra2[i] = Ap[i];
            const float* Bp = &Bs[s][k][tx * TN];
            float4 b0 = *(const float4*)Bp;
            float4 b1 = *(const float4*)(Bp + 4);
            u64 rb2[TN];
            rb2[0] = pack2(b0.x, b0.x); rb2[1] = pack2(b0.y, b0.y);
            rb2[2] = pack2(b0.z, b0.z); rb2[3] = pack2(b0.w, b0.w);
            rb2[4] = pack2(b1.x, b1.x); rb2[5] = pack2(b1.y, b1.y);
            rb2[6] = pack2(b1.z, b1.z); rb2[7] = pack2(b1.w, b1.w);
#pragma unroll
            for (int i = 0; i < TM/2; i++)
#pragma unroll
                for (int j = 0; j < TN; j++)
                    fma2(acc2[i][j], ra2[i], rb2[j]);
        }
    };

    // double-buffered pipeline: one __syncthreads per k-tile
    load_tile(0);
    store_tile(0);
    __syncthreads();
    int s = 0;
    for (int k0 = BK; k0 < K; k0 += BK) {
        load_tile(k0);         // GMEM loads for next stage in flight
        store_tile(s ^ 1);     // land them in the other buffer
        compute_tile(s);       // consume current buffer meanwhile
        __syncthreads();
        s ^= 1;
    }
    compute_tile(s);

    // epilogue: hoist bias terms and row base pointers
    float bterm[TN];
    int gn_base = n0 + tx * TN;
#pragma unroll
    for (int j = 0; j < TN; j++)
        bterm[j] = (gn_base + j < N) ? bias_scale * bias[gn_base + j] : 0.f;

#pragma unroll
    for (int i = 0; i < TM/2; i++) {
        int gm_lo = m0 + ty * TM + 2 * i;
        int gm_hi = gm_lo + 1;
        float* Clo = C + (size_t)gm_lo * N;
        float* Chi = C + (size_t)gm_hi * N;
        const float* Rlo = R ? R + (size_t)gm_lo * N : nullptr;
        const float* Rhi = R ? R + (size_t)gm_hi * N : nullptr;
#pragma unroll
        for (int j = 0; j < TN; j++) {
            int gn = gn_base + j;
            if (gn >= N) continue;
            float clo, chi;
            unpack2(acc2[i][j], clo, chi);
            if (gm_lo < M) {
                float c = clo + bterm[j];
                if (Rlo) c += res_scale * Rlo[gn];
                if (relu) c = fmaxf(c, 0.f);
                Clo[gn] = c;
            }
            if (gm_hi < M) {
                float c = chi + bterm[j];
                if (Rhi) c += res_scale * Rhi[gn];
                if (relu) c = fmaxf(c, 0.f);
                Chi[gn] = c;
            }
        }
    }
}

// ---------------- reference points: warp-per-query, N=2 --------------------
__global__ void ref_kernel(const float* __restrict__ q,
                           const float* __restrict__ Wr,
                           const float* __restrict__ br,
                           float* __restrict__ ref)
{
    int warp = (blockIdx.x * blockDim.x + threadIdx.x) >> 5;
    int lane = threadIdx.x & 31;
    if (warp >= NQ) return;
    const float* qr = q + (size_t)warp * D;
    float s0 = 0.f, s1 = 0.f;
    for (int j = lane; j < D; j += 32) {
        float qv = qr[j];
        s0 += qv * Wr[j * 2 + 0];
        s1 += qv * Wr[j * 2 + 1];
    }
#pragma unroll
    for (int o = 16; o; o >>= 1) {
        s0 += __shfl_xor_sync(0xffffffffu, s0, o);
        s1 += __shfl_xor_sync(0xffffffffu, s1, o);
    }
    if (lane == 0) {
        s0 += br[0]; s1 += br[1];
        ref[warp * 2 + 0] = 1.f / (1.f + expf(-s0));
        ref[warp * 2 + 1] = 1.f / (1.f + expf(-s1));
    }
}

// ---------------- deformable attention (fused softmax + bilinear gather) ----
__global__ void __launch_bounds__(256)
deform_kernel(const float* __restrict__ vsum, const float* __restrict__ ref,
              const float* __restrict__ off, const float* __restrict__ attnraw,
              float* __restrict__ out)
{
    const int q = blockIdx.x;
    const int h = threadIdx.x >> 5;
    const int lane = threadIdx.x & 31;

    const float refx = ref[q * 2 + 0];
    const float refy = ref[q * 2 + 1];

    float a = -1e30f, ox = 0.f, oy = 0.f;
    if (lane < NP) {
        a  = attnraw[(size_t)q * (NH*NP) + h * NP + lane];
        ox = off[(size_t)q * (NH*NP*2) + h * (NP*2) + lane * 2 + 0];
        oy = off[(size_t)q * (NH*NP*2) + h * (NP*2) + lane * 2 + 1];
    }
    float m = a;
#pragma unroll
    for (int o = 4; o; o >>= 1) m = fmaxf(m, __shfl_xor_sync(0xffffffffu, m, o));
    float e = expf(a - m);
    float s = e;
#pragma unroll
    for (int o = 4; o; o >>= 1) s += __shfl_xor_sync(0xffffffffu, s, o);
    float w = e / s;

    float locx = refx + ox * (1.f / (float)BEVW);
    float locy = refy + oy * (1.f / (float)BEVH);

    float accv = 0.f;
    const float* vh = vsum + h * HD + lane;
#pragma unroll
    for (int p = 0; p < NP; p++) {
        float x  = __shfl_sync(0xffffffffu, locx, p);
        float y  = __shfl_sync(0xffffffffu, locy, p);
        float wa = __shfl_sync(0xffffffffu, w,    p);
        x = x * (float)BEVW - 0.5f;
        y = y * (float)BEVH - 0.5f;
        float xf = floorf(x), yf = floorf(y);
        float lx = x - xf, ly = y - yf;
        int x0 = (int)xf, y0 = (int)yf;
#pragma unroll
        for (int c = 0; c < 4; c++) {
            int dx = c & 1, dy = c >> 1;
            int ix = x0 + dx, iy = y0 + dy;
            if (ix < 0 || ix >= BEVW || iy < 0 || iy >= BEVH) continue;
            float wc = (dx ? lx : 1.f - lx) * (dy ? ly : 1.f - ly) * wa;
            accv += wc * vh[(size_t)(iy * BEVW + ix) * D];
        }
    }
    out[(size_t)q * D + h * HD + lane] = accv;
}

// ---------------- host launcher --------------------------------------------
extern "C" void kernel_launch(void* const* d_in, const int* in_sizes, int n_in,
                              void* d_out, int out_size)
{
    (void)in_sizes; (void)n_in; (void)out_size;
    const float* B0    = (const float*)d_in[0];
    const float* B1    = (const float*)d_in[1];
    const float* q     = (const float*)d_in[2];
    const float* Wref  = (const float*)d_in[3];
    const float* bref  = (const float*)d_in[4];
    const float* Woff  = (const float*)d_in[5];
    const float* boff  = (const float*)d_in[6];
    const float* Wattn = (const float*)d_in[7];
    const float* battn = (const float*)d_in[8];
    const float* Wval  = (const float*)d_in[9];
    const float* bval  = (const float*)d_in[10];
    const float* Wout  = (const float*)d_in[11];
    const float* bout  = (const float*)d_in[12];
    const float* Wff1  = (const float*)d_in[13];
    const float* bff1  = (const float*)d_in[14];
    const float* Wff2  = (const float*)d_in[15];
    const float* bff2  = (const float*)d_in[16];
    float* out = (float*)d_out;

    float *p_off, *p_attn, *p_ref, *p_vsum, *p_att, *p_ffh;
    cudaGetSymbolAddress((void**)&p_off,  g_off);
    cudaGetSymbolAddress((void**)&p_attn, g_attn);
    cudaGetSymbolAddress((void**)&p_ref,  g_ref);
    cudaGetSymbolAddress((void**)&p_vsum, g_vsum);
    cudaGetSymbolAddress((void**)&p_att,  g_att);
    cudaGetSymbolAddress((void**)&p_ffh,  g_ffh);

    const int MB = (NQ + BM - 1) / BM;  // 313

    // 1) off = q @ W_off + b_off            [40000 x 128]
    gemm_kernel<<<dim3(1, MB), 256>>>(q, nullptr, Woff, boff, 1.f,
                                      nullptr, 0.f, 0, p_off, NQ, NH*NP*2, D);
    // 2) attnraw = q @ W_attn + b_attn      [40000 x 64]
    gemm_kernel<<<dim3(1, MB), 256>>>(q, nullptr, Wattn, battn, 1.f,
                                      nullptr, 0.f, 0, p_attn, NQ, NH*NP, D);
    // 3) ref = sigmoid(q @ W_ref + b_ref)   [40000 x 2]
    ref_kernel<<<(NQ * 32 + 255) / 256, 256>>>(q, Wref, bref, p_ref);

    // 4) vsum = (B0 + B1) @ W_val + 2*b_val [40000 x 256]
    //    (deform is linear in value => one GEMM + one gather for both branches)
    gemm_kernel<<<dim3(D/BN, MB), 256>>>(B0, B1, Wval, bval, 2.f,
                                         nullptr, 0.f, 0, p_vsum, NQ, D, D);
    // 5) attended-sum via fused softmax + bilinear gather
    deform_kernel<<<NQ, 256>>>(p_vsum, p_ref, p_off, p_attn, p_att);

    // 6) B_short = att @ W_out + 2*b_out + 2*q   -> d_out
    gemm_kernel<<<dim3(D/BN, MB), 256>>>(p_att, nullptr, Wout, bout, 2.f,
                                         q, 2.f, 0, out, NQ, D, D);
    // 7) h = relu(B_short @ W_ffn1 + b_ffn1)     [40000 x 1024]
    gemm_kernel<<<dim3(DFF/BN, MB), 256>>>(out, nullptr, Wff1, bff1, 1.f,
                                           nullptr, 0.f, 1, p_ffh, NQ, DFF, D);
    // 8) out = h @ W_ffn2 + b_ffn2 + B_short     -> d_out (in-place residual)
    gemm_kernel<<<dim3(D/BN, MB), 256>>>(p_ffh, nullptr, Wff2, bff2, 1.f,
                                         out, 1.f, 0, out, NQ, D, DFF);
}

// round 16
// speedup vs baseline: 1.0418x; 1.0418x over previous
#include <cuda_runtime.h>
#include <cstddef>

#define NQ    40000
#define D     256
#define BEVH  200
#define BEVW  200
#define NH    8
#define NP    8
#define HD    32
#define DFF   1024

typedef unsigned long long u64;

// ---------------- scratch (static device globals; no allocation) ------------
__device__ float g_off [ (size_t)NQ * (NH*NP*2) ];   // 40000 x 128
__device__ float g_attn[ (size_t)NQ * (NH*NP)   ];   // 40000 x 64
__device__ float g_ref [ (size_t)NQ * 2         ];   // 40000 x 2
__device__ float g_vsum[ (size_t)NQ * D         ];   // 40000 x 256 (val0+val1)
__device__ float g_att [ (size_t)NQ * D         ];   // 40000 x 256 (attended sum)
__device__ float g_ffh [ (size_t)NQ * DFF       ];   // 40000 x 1024

// ---------------- f32x2 packed-FMA helpers (sm_103a FFMA2) ------------------
__device__ __forceinline__ u64 pack2(float lo, float hi) {
    u64 r;
    asm("mov.b64 %0, {%1, %2};" : "=l"(r) : "f"(lo), "f"(hi));
    return r;
}
__device__ __forceinline__ void unpack2(u64 v, float& lo, float& hi) {
    asm("mov.b64 {%0, %1}, %2;" : "=f"(lo), "=f"(hi) : "l"(v));
}
__device__ __forceinline__ void fma2(u64& d, u64 a, u64 b) {
    asm("fma.rn.f32x2 %0, %1, %2, %0;" : "+l"(d) : "l"(a), "l"(b));
}

// ---------------- tiled fp32 GEMM, f32x2 inner product, fused epilogue ------
// C[M,N] = (A (+A2)) @ W[K,N] + bias_scale*bias + res_scale*R ; optional relu
// 128x128 block tile, 256 threads, 8x8 micro-tile (f32x2 pairs along M),
// double-buffered smem. Pipeline order: LDG(k+1) -> compute(k) -> STS(k+1),
// so global loads are in flight across the whole compute phase and the
// dependent shared stores execute after the latency is covered.
#define BM 128
#define BN 128
#define BK 16
#define TM 8
#define TN 8
#define ASTRIDE (BM + 2)   // +2 pad: conflict-free transposed stores, 8B-aligned reads

__global__ void __launch_bounds__(256, 2)
gemm_kernel(const float* __restrict__ A, const float* __restrict__ A2,
            const float* __restrict__ W, const float* __restrict__ bias,
            float bias_scale,
            const float* __restrict__ R, float res_scale, int relu,
            float* __restrict__ C, int M, int N, int K)
{
    __shared__ float As[2][BK][ASTRIDE];   // As[s][k][m]
    __shared__ float Bs[2][BK][BN];        // Bs[s][k][n]
    const int tid = threadIdx.x;
    const int tx = tid & 15;        // 0..15 -> N (8 cols each)
    const int ty = tid >> 4;        // 0..15 -> M (8 rows each)
    const int m0 = blockIdx.y * BM;
    const int n0 = blockIdx.x * BN;

    u64 acc2[TM/2][TN];
#pragma unroll
    for (int i = 0; i < TM/2; i++)
#pragma unroll
        for (int j = 0; j < TN; j++) acc2[i][j] = 0ull;

    // A-tile loader: 2 float4 per thread. W-tile loader: 2 float4 per thread.
    const int a_row = tid >> 2;          // 0..63
    const int a_col = (tid & 3) * 4;     // 0,4,8,12
    const int w_row = tid >> 4;          // 0..15
    const int w_col = (tid & 15) * 8;    // 0..120

    float4 av[2], wv[2];

    auto load_tile = [&](int k0) {
#pragma unroll
        for (int r = 0; r < 2; r++) {
            int gm = m0 + a_row + r * 64;
            float4 v = make_float4(0.f, 0.f, 0.f, 0.f);
            if (gm < M) {
                v = *(const float4*)&A[(size_t)gm * K + k0 + a_col];
                if (A2) {
                    float4 v2 = *(const float4*)&A2[(size_t)gm * K + k0 + a_col];
                    v.x += v2.x; v.y += v2.y; v.z += v2.z; v.w += v2.w;
                }
            }
            av[r] = v;
        }
#pragma unroll
        for (int r = 0; r < 2; r++) {
            int gn = n0 + w_col + r * 4;
            wv[r] = (gn < N)
                ? *(const float4*)&W[(size_t)(k0 + w_row) * N + gn]
                : make_float4(0.f, 0.f, 0.f, 0.f);
        }
    };
    auto store_tile = [&](int s) {
#pragma unroll
        for (int r = 0; r < 2; r++) {
            As[s][a_col + 0][a_row + r * 64] = av[r].x;
            As[s][a_col + 1][a_row + r * 64] = av[r].y;
            As[s][a_col + 2][a_row + r * 64] = av[r].z;
            As[s][a_col + 3][a_row + r * 64] = av[r].w;
        }
        *(float4*)&Bs[s][w_row][w_col]     = wv[0];
        *(float4*)&Bs[s][w_row][w_col + 4] = wv[1];
    };
    auto compute_tile = [&](int s) {
#pragma unroll
        for (int k = 0; k < BK; k++) {
            const u64* Ap = (const u64*)&As[s][k][ty * TM];
            u64 ra2[TM/2];
#pragma unroll
            for (int i = 0; i < TM/2; i++) ra2[i] = Ap[i];
            const float* Bp = &Bs[s][k][tx * TN];
            float4 b0 = *(const float4*)Bp;
            float4 b1 = *(const float4*)(Bp + 4);
            u64 rb2[TN];
            rb2[0] = pack2(b0.x, b0.x); rb2[1] = pack2(b0.y, b0.y);
            rb2[2] = pack2(b0.z, b0.z); rb2[3] = pack2(b0.w, b0.w);
            rb2[4] = pack2(b1.x, b1.x); rb2[5] = pack2(b1.y, b1.y);
            rb2[6] = pack2(b1.z, b1.z); rb2[7] = pack2(b1.w, b1.w);
#pragma unroll
            for (int i = 0; i < TM/2; i++)
#pragma unroll
                for (int j = 0; j < TN; j++)
                    fma2(acc2[i][j], ra2[i], rb2[j]);
        }
    };

    // double-buffered pipeline, loads overlap compute:
    //   LDG(stage k+1) ; FFMA2 on stage k ; STS(stage k+1) ; sync
    load_tile(0);
    store_tile(0);
    __syncthreads();
    int s = 0;
    for (int k0 = BK; k0 < K; k0 += BK) {
        load_tile(k0);         // GMEM loads for next stage go in flight
        compute_tile(s);       // ~512 fma-pipe cycles cover the LDG latency
        store_tile(s ^ 1);     // dependent STS lands after latency is hidden
        __syncthreads();
        s ^= 1;
    }
    compute_tile(s);

    // epilogue: hoist bias terms and row base pointers
    float bterm[TN];
    int gn_base = n0 + tx * TN;
#pragma unroll
    for (int j = 0; j < TN; j++)
        bterm[j] = (gn_base + j < N) ? bias_scale * bias[gn_base + j] : 0.f;

#pragma unroll
    for (int i = 0; i < TM/2; i++) {
        int gm_lo = m0 + ty * TM + 2 * i;
        int gm_hi = gm_lo + 1;
        float* Clo = C + (size_t)gm_lo * N;
        float* Chi = C + (size_t)gm_hi * N;
        const float* Rlo = R ? R + (size_t)gm_lo * N : nullptr;
        const float* Rhi = R ? R + (size_t)gm_hi * N : nullptr;
#pragma unroll
        for (int j = 0; j < TN; j++) {
            int gn = gn_base + j;
            if (gn >= N) continue;
            float clo, chi;
            unpack2(acc2[i][j], clo, chi);
            if (gm_lo < M) {
                float c = clo + bterm[j];
                if (Rlo) c += res_scale * Rlo[gn];
                if (relu) c = fmaxf(c, 0.f);
                Clo[gn] = c;
            }
            if (gm_hi < M) {
                float c = chi + bterm[j];
                if (Rhi) c += res_scale * Rhi[gn];
                if (relu) c = fmaxf(c, 0.f);
                Chi[gn] = c;
            }
        }
    }
}

// ---------------- reference points: warp-per-query, N=2 --------------------
__global__ void ref_kernel(const float* __restrict__ q,
                           const float* __restrict__ Wr,
                           const float* __restrict__ br,
                           float* __restrict__ ref)
{
    int warp = (blockIdx.x * blockDim.x + threadIdx.x) >> 5;
    int lane = threadIdx.x & 31;
    if (warp >= NQ) return;
    const float* qr = q + (size_t)warp * D;
    float s0 = 0.f, s1 = 0.f;
    for (int j = lane; j < D; j += 32) {
        float qv = qr[j];
        s0 += qv * Wr[j * 2 + 0];
        s1 += qv * Wr[j * 2 + 1];
    }
#pragma unroll
    for (int o = 16; o; o >>= 1) {
        s0 += __shfl_xor_sync(0xffffffffu, s0, o);
        s1 += __shfl_xor_sync(0xffffffffu, s1, o);
    }
    if (lane == 0) {
        s0 += br[0]; s1 += br[1];
        ref[warp * 2 + 0] = 1.f / (1.f + expf(-s0));
        ref[warp * 2 + 1] = 1.f / (1.f + expf(-s1));
    }
}

// ---------------- deformable attention (fused softmax + bilinear gather) ----
__global__ void __launch_bounds__(256)
deform_kernel(const float* __restrict__ vsum, const float* __restrict__ ref,
              const float* __restrict__ off, const float* __restrict__ attnraw,
              float* __restrict__ out)
{
    const int q = blockIdx.x;
    const int h = threadIdx.x >> 5;
    const int lane = threadIdx.x & 31;

    const float refx = ref[q * 2 + 0];
    const float refy = ref[q * 2 + 1];

    float a = -1e30f, ox = 0.f, oy = 0.f;
    if (lane < NP) {
        a  = attnraw[(size_t)q * (NH*NP) + h * NP + lane];
        ox = off[(size_t)q * (NH*NP*2) + h * (NP*2) + lane * 2 + 0];
        oy = off[(size_t)q * (NH*NP*2) + h * (NP*2) + lane * 2 + 1];
    }
    float m = a;
#pragma unroll
    for (int o = 4; o; o >>= 1) m = fmaxf(m, __shfl_xor_sync(0xffffffffu, m, o));
    float e = expf(a - m);
    float s = e;
#pragma unroll
    for (int o = 4; o; o >>= 1) s += __shfl_xor_sync(0xffffffffu, s, o);
    float w = e / s;

    float locx = refx + ox * (1.f / (float)BEVW);
    float locy = refy + oy * (1.f / (float)BEVH);

    float accv = 0.f;
    const float* vh = vsum + h * HD + lane;
#pragma unroll
    for (int p = 0; p < NP; p++) {
        float x  = __shfl_sync(0xffffffffu, locx, p);
        float y  = __shfl_sync(0xffffffffu, locy, p);
        float wa = __shfl_sync(0xffffffffu, w,    p);
        x = x * (float)BEVW - 0.5f;
        y = y * (float)BEVH - 0.5f;
        float xf = floorf(x), yf = floorf(y);
        float lx = x - xf, ly = y - yf;
        int x0 = (int)xf, y0 = (int)yf;
#pragma unroll
        for (int c = 0; c < 4; c++) {
            int dx = c & 1, dy = c >> 1;
            int ix = x0 + dx, iy = y0 + dy;
            if (ix < 0 || ix >= BEVW || iy < 0 || iy >= BEVH) continue;
            float wc = (dx ? lx : 1.f - lx) * (dy ? ly : 1.f - ly) * wa;
            accv += wc * vh[(size_t)(iy * BEVW + ix) * D];
        }
    }
    out[(size_t)q * D + h * HD + lane] = accv;
}

// ---------------- host launcher --------------------------------------------
extern "C" void kernel_launch(void* const* d_in, const int* in_sizes, int n_in,
                              void* d_out, int out_size)
{
    (void)in_sizes; (void)n_in; (void)out_size;
    const float* B0    = (const float*)d_in[0];
    const float* B1    = (const float*)d_in[1];
    const float* q     = (const float*)d_in[2];
    const float* Wref  = (const float*)d_in[3];
    const float* bref  = (const float*)d_in[4];
    const float* Woff  = (const float*)d_in[5];
    const float* boff  = (const float*)d_in[6];
    const float* Wattn = (const float*)d_in[7];
    const float* battn = (const float*)d_in[8];
    const float* Wval  = (const float*)d_in[9];
    const float* bval  = (const float*)d_in[10];
    const float* Wout  = (const float*)d_in[11];
    const float* bout  = (const float*)d_in[12];
    const float* Wff1  = (const float*)d_in[13];
    const float* bff1  = (const float*)d_in[14];
    const float* Wff2  = (const float*)d_in[15];
    const float* bff2  = (const float*)d_in[16];
    float* out = (float*)d_out;

    float *p_off, *p_attn, *p_ref, *p_vsum, *p_att, *p_ffh;
    cudaGetSymbolAddress((void**)&p_off,  g_off);
    cudaGetSymbolAddress((void**)&p_attn, g_attn);
    cudaGetSymbolAddress((void**)&p_ref,  g_ref);
    cudaGetSymbolAddress((void**)&p_vsum, g_vsum);
    cudaGetSymbolAddress((void**)&p_att,  g_att);
    cudaGetSymbolAddress((void**)&p_ffh,  g_ffh);

    const int MB = (NQ + BM - 1) / BM;  // 313

    // 1) off = q @ W_off + b_off            [40000 x 128]
    gemm_kernel<<<dim3(1, MB), 256>>>(q, nullptr, Woff, boff, 1.f,
                                      nullptr, 0.f, 0, p_off, NQ, NH*NP*2, D);
    // 2) attnraw = q @ W_attn + b_attn      [40000 x 64]
    gemm_kernel<<<dim3(1, MB), 256>>>(q, nullptr, Wattn, battn, 1.f,
                                      nullptr, 0.f, 0, p_attn, NQ, NH*NP, D);
    // 3) ref = sigmoid(q @ W_ref + b_ref)   [40000 x 2]
    ref_kernel<<<(NQ * 32 + 255) / 256, 256>>>(q, Wref, bref, p_ref);

    // 4) vsum = (B0 + B1) @ W_val + 2*b_val [40000 x 256]
    //    (deform is linear in value => one GEMM + one gather for both branches)
    gemm_kernel<<<dim3(D/BN, MB), 256>>>(B0, B1, Wval, bval, 2.f,
                                         nullptr, 0.f, 0, p_vsum, NQ, D, D);
    // 5) attended-sum via fused softmax + bilinear gather
    deform_kernel<<<NQ, 256>>>(p_vsum, p_ref, p_off, p_attn, p_att);

    // 6) B_short = att @ W_out + 2*b_out + 2*q   -> d_out
    gemm_kernel<<<dim3(D/BN, MB), 256>>>(p_att, nullptr, Wout, bout, 2.f,
                                         q, 2.f, 0, out, NQ, D, D);
    // 7) h = relu(B_short @ W_ffn1 + b_ffn1)     [40000 x 1024]
    gemm_kernel<<<dim3(DFF/BN, MB), 256>>>(out, nullptr, Wff1, bff1, 1.f,
                                           nullptr, 0.f, 1, p_ffh, NQ, DFF, D);
    // 8) out = h @ W_ffn2 + b_ffn2 + B_short     -> d_out (in-place residual)
    gemm_kernel<<<dim3(D/BN, MB), 256>>>(p_ffh, nullptr, Wff2, bff2, 1.f,
                                         out, 1.f, 0, out, NQ, D, DFF);
}